// round 4
// baseline (speedup 1.0000x reference)
#include <cuda_runtime.h>
#include <cuda_bf16.h>
#include <cstdint>

// Problem constants (reference: TRACK_SIZE=16, C=240 -> 15 tracks).
#define C_TOT   240
#define ROW_F4  60          // float4 per row
#define TJ      32          // output rows per CTA tile
#define TY      8           // blockDim.y
#define KPT     (TJ / TY)   // rows per thread (4)

// Pipeline per CTA: cp.async.cg gather (global->smem, bypasses L1/registers)
// -> single cp.async.bulk TMA store of the contiguous 30 KB output tile.
// row(j,t) = ((j + shift_t) % P) % L, P = 3*min(lengths), shift_t = 2^(t-1).
__global__ __launch_bounds__(480, 4) void rc_gather_cpasync_kernel(
    const float4* __restrict__ x,       // (B, N, 60) float4
    const int*    __restrict__ lengths, // (B,)
    float*        __restrict__ out,     // (B, max_len, 240) float
    int B, int N, int max_len)
{
    __shared__ __align__(16) float4 tile[TJ * ROW_F4];   // 30 KB

    const int q  = threadIdx.x;        // 0..59 : float4 column
    const int ty = threadIdx.y;        // 0..7
    const int b  = blockIdx.z;
    const int j0 = blockIdx.x * TJ;
    if (j0 >= max_len) return;

    // min(lengths): B tiny; L2-resident scalar loads.
    int minL = __ldg(lengths);
    #pragma unroll 4
    for (int i = 1; i < B; ++i) minL = min(minL, __ldg(lengths + i));
    const int P = 3 * minL;
    const int L = __ldg(lengths + b);

    const int t     = q >> 2;              // track 0..14
    const int shift = (1u << t) >> 1;      // 0,1,2,4,...,2^13

    const float4* __restrict__ src = x + (size_t)b * N * ROW_F4 + q;
    const int nrows = min(TJ, max_len - j0);

    // Pre-wrapped base for this thread's first row (jl = ty).
    int v0 = j0 + ty + shift;
    while (v0 >= P) v0 -= P;

    uint32_t sbase;
    asm("{ .reg .u64 tt; cvta.to.shared.u64 tt, %1; cvt.u32.u64 %0, tt; }"
        : "=r"(sbase) : "l"(tile));
    const uint32_t sthr = sbase + (uint32_t)(ty * ROW_F4 + q) * 16u;

    // Gather: one cp.async.cg (16 B) per (row, chunk); 4 in flight per thread.
    #pragma unroll
    for (int k = 0; k < KPT; ++k) {
        const int jl = ty + TY * k;
        int v = v0 + TY * k;
        if (v >= P) v -= P;                // TY*KPT << P: at most one wrap
        int r = v;
        while (r >= L) r -= L;             // v < 3L: <=2 iters
        if (jl < nrows) {
            const float4* gsrc = src + (size_t)r * ROW_F4;
            const uint32_t sdst = sthr + (uint32_t)(TY * k * ROW_F4) * 16u;
            asm volatile(
                "cp.async.cg.shared.global [%0], [%1], 16;"
                :: "r"(sdst), "l"(gsrc) : "memory");
        }
    }
    asm volatile("cp.async.commit_group;" ::: "memory");
    asm volatile("cp.async.wait_group 0;" ::: "memory");
    __syncthreads();

    // One bulk TMA store of the whole contiguous tile (smem -> gmem via L2).
    if (threadIdx.x == 0 && threadIdx.y == 0) {
        asm volatile("fence.proxy.async.shared::cta;" ::: "memory");
        float* gdst = out + ((size_t)b * max_len + j0) * C_TOT;
        const int bytes = nrows * ROW_F4 * 16;   // multiple of 16
        asm volatile(
            "cp.async.bulk.global.shared::cta.bulk_group [%0], [%1], %2;"
            :: "l"(gdst), "r"(sbase), "r"(bytes) : "memory");
        asm volatile("cp.async.bulk.commit_group;" ::: "memory");
        asm volatile("cp.async.bulk.wait_group 0;" ::: "memory");
    }
}

extern "C" void kernel_launch(void* const* d_in, const int* in_sizes, int n_in,
                              void* d_out, int out_size) {
    const float* x       = (const float*)d_in[0];
    const int*   lengths = (const int*)d_in[1];
    float*       out     = (float*)d_out;

    const int B = in_sizes[1];                    // 8
    const int N = in_sizes[0] / (B * C_TOT);      // 16384
    const int max_len = out_size / (B * C_TOT);   // max(lengths)

    dim3 blk(ROW_F4, TY, 1);                      // 480 threads
    dim3 grid((max_len + TJ - 1) / TJ, 1, B);     // (512,1,8)
    rc_gather_cpasync_kernel<<<grid, blk>>>((const float4*)x, lengths, out,
                                            B, N, max_len);
}

// round 5
// speedup vs baseline: 1.0447x; 1.0447x over previous
#include <cuda_runtime.h>
#include <cuda_bf16.h>
#include <cstdint>

// Problem constants (reference: TRACK_SIZE=16, C=240 -> 15 tracks).
#define C_TOT   240
#define ROW_F4  60          // float4 per row
#define TJ      32          // input rows per CTA tile
#define TY      8           // blockDim.y
#define KPT     (TJ / TY)   // rows per thread (4)

// Input-major scatter: CTA reads input rows [r0, r0+32) fully coalesced
// (each byte read from DRAM exactly once; rows >= L skipped entirely),
// then scatters each 16B chunk to its 1-3 output positions.
// Forward map: out[j] = x[((j+shift_t)%P)%L]; inverse: for v in
// {r, r+L, r+2L} with v<P, j = v-shift (+P for the P-wrap case).
__global__ __launch_bounds__(480, 4) void rc_scatter_kernel(
    const float4* __restrict__ x,       // (B, N, 60) float4
    const int*    __restrict__ lengths, // (B,)
    float4*       __restrict__ out,     // (B, max_len, 60) float4
    int B, int N, int max_len)
{
    const int b  = blockIdx.z;
    const int L  = __ldg(lengths + b);
    const int r0 = blockIdx.x * TJ;
    if (r0 >= L) return;                 // rows >= L are never used

    // min(lengths): B tiny; L2-resident scalar loads.
    int minL = __ldg(lengths);
    #pragma unroll 4
    for (int i = 1; i < B; ++i) minL = min(minL, __ldg(lengths + i));
    const int P = 3 * minL;

    const int q  = threadIdx.x;          // 0..59 : float4 column
    const int ty = threadIdx.y;          // 0..7
    const int t     = q >> 2;            // track 0..14
    const int shift = (1u << t) >> 1;    // 0,1,2,4,...,2^13

    const float4* __restrict__ src = x + ((size_t)b * N + r0) * ROW_F4 + q;
    float4* __restrict__ dst = out + (size_t)b * max_len * ROW_F4 + q;

    // Phase 1: fully-coalesced sequential reads (evict-first: zero reuse).
    float4 v[KPT];
    int    rr[KPT];
    #pragma unroll
    for (int k = 0; k < KPT; ++k) {
        const int rl = ty + TY * k;
        rr[k] = r0 + rl;
        if (rr[k] < L)
            v[k] = __ldcs(src + (size_t)rl * ROW_F4);
    }

    // Phase 2: scatter each chunk to its output positions.
    #pragma unroll
    for (int k = 0; k < KPT; ++k) {
        const int r = rr[k];
        if (r >= L) continue;
        #pragma unroll
        for (int m = 0; m < 3; ++m) {
            const int vv = r + m * L;
            if (vv < P) {
                const int j = vv - shift;
                if (j >= 0 && j < max_len)
                    dst[(size_t)j * ROW_F4] = v[k];
                const int j2 = j + P;    // P-wrap generality
                if (j2 >= 0 && j2 < max_len)
                    dst[(size_t)j2 * ROW_F4] = v[k];
            }
        }
    }
}

extern "C" void kernel_launch(void* const* d_in, const int* in_sizes, int n_in,
                              void* d_out, int out_size) {
    const float* x       = (const float*)d_in[0];
    const int*   lengths = (const int*)d_in[1];
    float*       out     = (float*)d_out;

    const int B = in_sizes[1];                    // 8
    const int N = in_sizes[0] / (B * C_TOT);      // 16384
    const int max_len = out_size / (B * C_TOT);   // max(lengths)

    dim3 blk(ROW_F4, TY, 1);                      // 480 threads
    dim3 grid((N + TJ - 1) / TJ, 1, B);           // (512,1,8); tail CTAs exit
    rc_scatter_kernel<<<grid, blk>>>((const float4*)x, lengths, (float4*)out,
                                     B, N, max_len);
}